// round 5
// baseline (speedup 1.0000x reference)
#include <cuda_runtime.h>
#include <cstdint>

// HashEmbeddingEncoder: out[n, l*8+f] = sign(tables[l, hash3d(cell(n,l)) & (2^19-1), f])
//
//  - gridDim.y = level (12), gridDim.x = point blocks. x-major launch order keeps
//    one 16MB level table L2-resident at a time (table+coords = 28MB << 126MB L2).
//  - hash entirely in uint32: (h mod 2^19) depends only on low 19 bits; cell
//    indices are clamped >= 0 so the int64 reference path agrees.
//  - table loads via __ldcg (L2 only; random 32B gathers have ~0 L1 hit rate).
//  - output stored with __stcs (streaming) so the 384MB write stream does not
//    evict the level table from L2.
//  - all offsets in 32-bit (max 96M elements < 2^31).

#define NUM_LEVELS 12
#define FEAT 8
#define TABLE_SIZE (1u << 19)
#define TABLE_MASK (TABLE_SIZE - 1u)
#define P1 2654435761u
#define P2 805459861u

__constant__ int c_res[NUM_LEVELS] = {16, 21, 30, 41, 56, 77, 105, 145, 198, 272, 373, 512};

static __device__ __forceinline__ float sgn(float v) {
    // matches jnp.sign: -1 / 0 / +1
    return (float)(v > 0.0f) - (float)(v < 0.0f);
}

__global__ void __launch_bounds__(256) hash_encode_kernel(
    const float* __restrict__ coords,   // [N, 3]
    const float* __restrict__ tables,   // [12, 2^19, 8]
    float* __restrict__ out,            // [N, 96]
    int n)
{
    const int p = blockIdx.x * blockDim.x + threadIdx.x;
    const int l = blockIdx.y;
    if (p >= n) return;

    const uint32_t pc = 3u * (uint32_t)p;
    const float x = coords[pc + 0];
    const float y = coords[pc + 1];
    const float z = coords[pc + 2];

    const int res = c_res[l];
    const float rf = (float)res;

    int cx = (int)floorf(x * rf);
    int cy = (int)floorf(y * rf);
    int cz = (int)floorf(z * rf);
    cx = min(max(cx, 0), res - 1);
    cy = min(max(cy, 0), res - 1);
    cz = min(max(cz, 0), res - 1);

    const uint32_t h   = (uint32_t)cx ^ ((uint32_t)cy * P1) ^ ((uint32_t)cz * P2);
    const uint32_t idx = h & TABLE_MASK;

    // 32-byte entry, 32B-aligned: exactly one L2 sector per gather.
    const float4* entry = reinterpret_cast<const float4*>(
        tables + (((uint32_t)l * TABLE_SIZE + idx) * FEAT));
    const float4 a = __ldcg(entry + 0);
    const float4 b = __ldcg(entry + 1);

    const float4 s0 = make_float4(sgn(a.x), sgn(a.y), sgn(a.z), sgn(a.w));
    const float4 s1 = make_float4(sgn(b.x), sgn(b.y), sgn(b.z), sgn(b.w));

    // single base IMAD; two STG.128 at [base] and [base+16]
    float4* o = reinterpret_cast<float4*>(
        out + ((uint32_t)p * (uint32_t)(NUM_LEVELS * FEAT) + (uint32_t)(l * FEAT)));
    __stcs(o + 0, s0);   // streaming store: keep table resident in L2
    __stcs(o + 1, s1);
}

extern "C" void kernel_launch(void* const* d_in, const int* in_sizes, int n_in,
                              void* d_out, int out_size)
{
    const float* coords = (const float*)d_in[0];   // [N,3] float32
    const float* tables = (const float*)d_in[1];   // [12, 2^19, 8] float32
    float* out = (float*)d_out;                    // [N, 96] float32

    const int n = in_sizes[0] / 3;

    dim3 block(256, 1, 1);
    dim3 grid((n + 255) / 256, NUM_LEVELS, 1);
    hash_encode_kernel<<<grid, block>>>(coords, tables, out, n);
}

// round 8
// speedup vs baseline: 2.4875x; 2.4875x over previous
#include <cuda_runtime.h>
#include <cstdint>

// HashEmbeddingEncoder, two-pass:
//  Pass 1: pack sign(tables) into 2-bit codes (uint16 per entry). 12MB total,
//          L2-resident for pass 2. Coalesced streaming read of 192MB.
//  Pass 2: per (32-point x 12-level) block: hashed uint16 gathers (one LDG.U16
//          per (p,l) instead of 2x LDG.128), decode to {-1,0,+1} floats, stage
//          in padded smem, write out fully coalesced with __stcs.
// Rationale: round-5 ncu showed L1tex wavefront divergence (scattered 384B-stride
// stores + 2x scattered gathers) was the limiter (L1 52.8%, DRAM only 23%).

#define NUM_LEVELS 12
#define FEAT 8
#define TABLE_SIZE (1u << 19)
#define TABLE_MASK (TABLE_SIZE - 1u)
#define P1 2654435761u
#define P2 805459861u

#define PTS_PER_BLK 32
#define ROW_PAD 100          // 96 floats + 4 pad: conflict-free STS.128 phases
#define ENC_THREADS (PTS_PER_BLK * NUM_LEVELS)   // 384

__constant__ int c_res[NUM_LEVELS] = {16, 21, 30, 41, 56, 77, 105, 145, 198, 272, 373, 512};

// 2-bit sign codes: 00=0, 01=+1, 11=-1 (two's-complement 2-bit). 12.6MB scratch.
__device__ uint16_t g_packed[NUM_LEVELS * TABLE_SIZE];

__global__ void __launch_bounds__(256) pack_signs_kernel(const float* __restrict__ tables)
{
    const uint32_t e = blockIdx.x * 256u + threadIdx.x;
    if (e >= NUM_LEVELS * TABLE_SIZE) return;

    const float4* src = reinterpret_cast<const float4*>(tables) + 2u * e;
    const float4 a = __ldcs(src + 0);   // streaming: no reuse of raw tables
    const float4 b = __ldcs(src + 1);

    const float v[8] = {a.x, a.y, a.z, a.w, b.x, b.y, b.z, b.w};
    uint32_t w = 0;
#pragma unroll
    for (int i = 0; i < 8; i++) {
        const uint32_t c = (v[i] > 0.0f) ? 1u : ((v[i] < 0.0f) ? 3u : 0u);
        w |= c << (2 * i);
    }
    g_packed[e] = (uint16_t)w;          // default store: keep resident in L2
}

__global__ void __launch_bounds__(ENC_THREADS) hash_encode_kernel(
    const float* __restrict__ coords,   // [N, 3]
    float* __restrict__ out,            // [N, 96]
    int n)
{
    __shared__ float s_coords[PTS_PER_BLK * 3];
    __shared__ float s_out[PTS_PER_BLK * ROW_PAD];

    const int t  = threadIdx.x;
    const int p0 = blockIdx.x * PTS_PER_BLK;

    // Stage 32 points' coords (384B coalesced).
    if (t < PTS_PER_BLK * 3) {
        const int gi = p0 * 3 + t;
        s_coords[t] = (gi < n * 3) ? coords[gi] : 0.0f;
    }
    __syncthreads();

    const int l  = t >> 5;      // warp id = level  -> uniform per warp
    const int pl = t & 31;      // lane    = point within tile
    const int p  = p0 + pl;

    {
        const float x = s_coords[pl * 3 + 0];
        const float y = s_coords[pl * 3 + 1];
        const float z = s_coords[pl * 3 + 2];

        const int res = c_res[l];
        const float rf = (float)res;
        int cx = min(max((int)floorf(x * rf), 0), res - 1);
        int cy = min(max((int)floorf(y * rf), 0), res - 1);
        int cz = min(max((int)floorf(z * rf), 0), res - 1);

        const uint32_t h   = (uint32_t)cx ^ ((uint32_t)cy * P1) ^ ((uint32_t)cz * P2);
        const uint32_t idx = h & TABLE_MASK;

        // Single 2-byte gather; 12MB packed table is fully L2-resident.
        const uint16_t* __restrict__ pk = g_packed;
        const uint32_t w = (p < n) ? (uint32_t)pk[((uint32_t)l << 19) + idx] : 0u;

        // Decode 2-bit codes -> {-1, 0, +1} floats.
        float f[8];
#pragma unroll
        for (int i = 0; i < 8; i++)
            f[i] = (float)((int)(w << (30 - 2 * i)) >> 30);

        // Padded smem row: stride 100 words -> conflict-free STS.128 phases.
        float4* dst = reinterpret_cast<float4*>(&s_out[pl * ROW_PAD + l * FEAT]);
        dst[0] = make_float4(f[0], f[1], f[2], f[3]);
        dst[1] = make_float4(f[4], f[5], f[6], f[7]);
    }
    __syncthreads();

    // Coalesced tile writeout: 32 pts x 96 floats = 768 float4s; 2 per thread.
    // q in float4 units; 24 float4 per logical 96-float row.
#pragma unroll
    for (int r = 0; r < 2; r++) {
        const int q  = t + r * ENC_THREADS;
        const int pp = q / 24;          // point within tile
        const int c4 = q % 24;          // float4 within row
        const float4 v = *reinterpret_cast<const float4*>(&s_out[pp * ROW_PAD + c4 * 4]);
        const int gp = p0 + pp;
        if (gp < n)
            __stcs(reinterpret_cast<float4*>(out + (uint32_t)gp * 96u) + c4, v);
    }
}

extern "C" void kernel_launch(void* const* d_in, const int* in_sizes, int n_in,
                              void* d_out, int out_size)
{
    const float* coords = (const float*)d_in[0];   // [N,3] float32
    const float* tables = (const float*)d_in[1];   // [12, 2^19, 8] float32
    float* out = (float*)d_out;                    // [N, 96] float32

    const int n = in_sizes[0] / 3;

    const int total_entries = NUM_LEVELS * TABLE_SIZE;
    pack_signs_kernel<<<(total_entries + 255) / 256, 256>>>(tables);

    const int nblk = (n + PTS_PER_BLK - 1) / PTS_PER_BLK;
    hash_encode_kernel<<<nblk, ENC_THREADS>>>(coords, out, n);
}

// round 10
// speedup vs baseline: 2.6408x; 1.0616x over previous
#include <cuda_runtime.h>
#include <cstdint>

// HashEmbeddingEncoder, two-pass:
//  Pass 1: pack sign(tables) into 2-bit codes (uint16 per entry). 12MB total,
//          L2-resident for pass 2. Coalesced streaming read of 192MB (~21us, DRAM-bound).
//  Pass 2: per 32-point tile: 384 threads gather one packed uint16 per (p,l),
//          stage the RAW WORDS in 768B of smem, then decode 2-bit codes ->
//          {-1,0,+1} floats inside the coalesced writeout threads.
// R8 ncu: L1tex 71.3% was the limiter; float staging (2xSTS.128+2xLDS.128 per
// (p,l)) was a big share. Staging uint16s cuts smem bytes 32x; decode moves to
// the writeout phase (alu had headroom at 26%).

#define NUM_LEVELS 12
#define FEAT 8
#define TABLE_SIZE (1u << 19)
#define TABLE_MASK (TABLE_SIZE - 1u)
#define P1 2654435761u
#define P2 805459861u

#define PTS_PER_BLK 32
#define ENC_THREADS (PTS_PER_BLK * NUM_LEVELS)   // 384

__constant__ int c_res[NUM_LEVELS] = {16, 21, 30, 41, 56, 77, 105, 145, 198, 272, 373, 512};

// 2-bit sign codes: 00=0, 01=+1, 11=-1 (two's-complement 2-bit). 12.6MB scratch.
__device__ uint16_t g_packed[NUM_LEVELS * TABLE_SIZE];

__global__ void __launch_bounds__(256) pack_signs_kernel(const float* __restrict__ tables)
{
    const uint32_t e = blockIdx.x * 256u + threadIdx.x;
    if (e >= NUM_LEVELS * TABLE_SIZE) return;

    const float4* src = reinterpret_cast<const float4*>(tables) + 2u * e;
    const float4 a = __ldcs(src + 0);   // streaming: raw tables never reused
    const float4 b = __ldcs(src + 1);

    const float v[8] = {a.x, a.y, a.z, a.w, b.x, b.y, b.z, b.w};
    uint32_t w = 0;
#pragma unroll
    for (int i = 0; i < 8; i++) {
        const uint32_t c = (v[i] > 0.0f) ? 1u : ((v[i] < 0.0f) ? 3u : 0u);
        w |= c << (2 * i);
    }
    g_packed[e] = (uint16_t)w;          // default store: stays resident in L2
}

// decode 2-bit code #k (k=0..7) of word w into -1/0/+1 float
static __device__ __forceinline__ float dec2(uint32_t w, int k) {
    return (float)((int)(w << (30 - 2 * k)) >> 30);
}

__global__ void __launch_bounds__(ENC_THREADS) hash_encode_kernel(
    const float* __restrict__ coords,   // [N, 3]
    float* __restrict__ out,            // [N, 96]
    int n)
{
    __shared__ float    s_coords[PTS_PER_BLK * 3];
    __shared__ uint16_t s_words[PTS_PER_BLK * NUM_LEVELS];   // 768 B

    const int t  = threadIdx.x;
    const int p0 = blockIdx.x * PTS_PER_BLK;

    // Stage 32 points' coords (384B coalesced).
    if (t < PTS_PER_BLK * 3) {
        const int gi = p0 * 3 + t;
        s_coords[t] = (gi < n * 3) ? coords[gi] : 0.0f;
    }
    __syncthreads();

    const int l  = t >> 5;      // warp id = level  -> uniform per warp
    const int pl = t & 31;      // lane    = point within tile
    const int p  = p0 + pl;

    {
        const float x = s_coords[pl * 3 + 0];
        const float y = s_coords[pl * 3 + 1];
        const float z = s_coords[pl * 3 + 2];

        const int res = c_res[l];
        const float rf = (float)res;
        int cx = min(max((int)floorf(x * rf), 0), res - 1);
        int cy = min(max((int)floorf(y * rf), 0), res - 1);
        int cz = min(max((int)floorf(z * rf), 0), res - 1);

        const uint32_t h   = (uint32_t)cx ^ ((uint32_t)cy * P1) ^ ((uint32_t)cz * P2);
        const uint32_t idx = h & TABLE_MASK;

        // Single 2-byte gather; 12MB packed table is fully L2-resident.
        const uint16_t* __restrict__ pk = g_packed;
        const uint16_t w = (p < n) ? pk[((uint32_t)l << 19) + idx] : (uint16_t)0;

        s_words[pl * NUM_LEVELS + l] = w;   // 2B per (p,l): tiny smem traffic
    }
    __syncthreads();

    // Coalesced writeout with inline decode: 32 pts x 24 float4 = 768 float4s,
    // 2 per thread. float4 #c4 of point pp covers level c4>>1, half c4&1.
#pragma unroll
    for (int r = 0; r < 2; r++) {
        const int q  = t + r * ENC_THREADS;
        const int pp = q / 24;              // point within tile
        const int c4 = q % 24;              // float4 within 96-float row
        const int lvl  = c4 >> 1;
        const int half = (c4 & 1) << 2;     // 0 or 4: which 4 codes

        const uint32_t w = (uint32_t)s_words[pp * NUM_LEVELS + lvl];
        const float4 v = make_float4(dec2(w, half + 0), dec2(w, half + 1),
                                     dec2(w, half + 2), dec2(w, half + 3));

        const int gp = p0 + pp;
        if (gp < n)
            __stcs(reinterpret_cast<float4*>(out + (uint32_t)gp * 96u) + c4, v);
    }
}

extern "C" void kernel_launch(void* const* d_in, const int* in_sizes, int n_in,
                              void* d_out, int out_size)
{
    const float* coords = (const float*)d_in[0];   // [N,3] float32
    const float* tables = (const float*)d_in[1];   // [12, 2^19, 8] float32
    float* out = (float*)d_out;                    // [N, 96] float32

    const int n = in_sizes[0] / 3;

    const int total_entries = NUM_LEVELS * TABLE_SIZE;
    pack_signs_kernel<<<(total_entries + 255) / 256, 256>>>(tables);

    const int nblk = (n + PTS_PER_BLK - 1) / PTS_PER_BLK;
    hash_encode_kernel<<<nblk, ENC_THREADS>>>(coords, out, n);
}

// round 14
// speedup vs baseline: 2.6892x; 1.0183x over previous
#include <cuda_runtime.h>
#include <cstdint>

// HashEmbeddingEncoder, two-pass:
//  Pass 1: pack sign(tables) into 2-bit codes (uint16/entry). 12MB, L2-resident.
//  Pass 2: 128-point tiles, 384 threads. Warp = level; each thread gathers 4
//          packed words (4 point-groups) -> 4 LDGs in flight per thread to
//          saturate the L1tex wavefront pipe (R10: pass2 at 96.7us vs ~62us
//          wavefront floor, issue only 42% with 1 gather/thread).
//          Words staged in smem (3KB), decode in coalesced writeout.

#define NUM_LEVELS 12
#define FEAT 8
#define TABLE_SIZE (1u << 19)
#define TABLE_MASK (TABLE_SIZE - 1u)
#define P1 2654435761u
#define P2 805459861u

#define PTS_PER_BLK 128
#define PT_GROUPS   4                      // points per thread in gather phase
#define ENC_THREADS 384

__constant__ int c_res[NUM_LEVELS] = {16, 21, 30, 41, 56, 77, 105, 145, 198, 272, 373, 512};

// 2-bit sign codes: 00=0, 01=+1, 11=-1 (two's-complement 2-bit). 12.6MB scratch.
__device__ uint16_t g_packed[NUM_LEVELS * TABLE_SIZE];

__global__ void __launch_bounds__(256) pack_signs_kernel(const float* __restrict__ tables)
{
    const uint32_t e = blockIdx.x * 256u + threadIdx.x;
    if (e >= NUM_LEVELS * TABLE_SIZE) return;

    const float4* src = reinterpret_cast<const float4*>(tables) + 2u * e;
    const float4 a = __ldcs(src + 0);   // streaming: raw tables never reused
    const float4 b = __ldcs(src + 1);

    const float v[8] = {a.x, a.y, a.z, a.w, b.x, b.y, b.z, b.w};
    uint32_t w = 0;
#pragma unroll
    for (int i = 0; i < 8; i++) {
        const uint32_t c = (v[i] > 0.0f) ? 1u : ((v[i] < 0.0f) ? 3u : 0u);
        w |= c << (2 * i);
    }
    g_packed[e] = (uint16_t)w;          // default store: stays resident in L2
}

// decode 2-bit code #k (k=0..7) of word w into -1/0/+1 float
static __device__ __forceinline__ float dec2(uint32_t w, int k) {
    return (float)((int)(w << (30 - 2 * k)) >> 30);
}

__global__ void __launch_bounds__(ENC_THREADS) hash_encode_kernel(
    const float* __restrict__ coords,   // [N, 3]
    float* __restrict__ out,            // [N, 96]
    int n)
{
    __shared__ float    s_coords[PTS_PER_BLK * 3];                 // 1.5 KB
    __shared__ uint16_t s_words[PTS_PER_BLK * NUM_LEVELS];         // 3 KB

    const int t  = threadIdx.x;
    const int p0 = blockIdx.x * PTS_PER_BLK;

    // Stage 128 points' coords (1536B coalesced, one float per thread).
    {
        const int gi = p0 * 3 + t;
        s_coords[t] = (gi < n * 3) ? coords[gi] : 0.0f;
    }
    __syncthreads();

    const int l    = t >> 5;            // warp id = level -> uniform per warp
    const int lane = t & 31;

    {
        const int res = c_res[l];
        const float rf = (float)res;
        const uint16_t* __restrict__ pk = g_packed + ((uint32_t)l << 19);

        // Compute 4 indices first, then issue 4 independent gathers (MLP=4).
        uint32_t idx[PT_GROUPS];
        bool     ok[PT_GROUPS];
#pragma unroll
        for (int k = 0; k < PT_GROUPS; k++) {
            const int pl = lane + k * 32;
            const float x = s_coords[pl * 3 + 0];
            const float y = s_coords[pl * 3 + 1];
            const float z = s_coords[pl * 3 + 2];
            int cx = min(max((int)floorf(x * rf), 0), res - 1);
            int cy = min(max((int)floorf(y * rf), 0), res - 1);
            int cz = min(max((int)floorf(z * rf), 0), res - 1);
            const uint32_t h = (uint32_t)cx ^ ((uint32_t)cy * P1) ^ ((uint32_t)cz * P2);
            idx[k] = h & TABLE_MASK;
            ok[k]  = (p0 + pl) < n;
        }

        uint16_t w[PT_GROUPS];
#pragma unroll
        for (int k = 0; k < PT_GROUPS; k++)
            w[k] = ok[k] ? pk[idx[k]] : (uint16_t)0;

#pragma unroll
        for (int k = 0; k < PT_GROUPS; k++)
            s_words[(lane + k * 32) * NUM_LEVELS + l] = w[k];
    }
    __syncthreads();

    // Coalesced writeout with inline decode: 128 pts x 24 float4 = 3072 float4s,
    // 8 per thread. float4 #c4 of point pp covers level c4>>1, codes half..half+3.
#pragma unroll
    for (int r = 0; r < 8; r++) {
        const int q  = t + r * ENC_THREADS;
        const int pp = q / 24;              // point within tile
        const int c4 = q % 24;              // float4 within 96-float row
        const int lvl  = c4 >> 1;
        const int half = (c4 & 1) << 2;

        const uint32_t w = (uint32_t)s_words[pp * NUM_LEVELS + lvl];
        const float4 v = make_float4(dec2(w, half + 0), dec2(w, half + 1),
                                     dec2(w, half + 2), dec2(w, half + 3));

        const int gp = p0 + pp;
        if (gp < n)
            __stcs(reinterpret_cast<float4*>(out + (uint32_t)gp * 96u) + c4, v);
    }
}

extern "C" void kernel_launch(void* const* d_in, const int* in_sizes, int n_in,
                              void* d_out, int out_size)
{
    const float* coords = (const float*)d_in[0];   // [N,3] float32
    const float* tables = (const float*)d_in[1];   // [12, 2^19, 8] float32
    float* out = (float*)d_out;                    // [N, 96] float32

    const int n = in_sizes[0] / 3;

    const int total_entries = NUM_LEVELS * TABLE_SIZE;
    pack_signs_kernel<<<(total_entries + 255) / 256, 256>>>(tables);

    const int nblk = (n + PTS_PER_BLK - 1) / PTS_PER_BLK;
    hash_encode_kernel<<<nblk, ENC_THREADS>>>(coords, out, n);
}